// round 1
// baseline (speedup 1.0000x reference)
#include <cuda_runtime.h>

#define NN 50000
#define EE 800000
#define DH 64

// ---- scratch (device globals; no allocation allowed) ----
__device__ float g_h[NN * DH];
__device__ float g_P[NN * DH];
__device__ float g_Q[NN * DH];
__device__ float g_agg[NN * DH];

// =====================================================================
// Input projection: h = x @ in_w + in_b   ([N,3] @ [3,64])
// =====================================================================
__global__ void k_input(const float* __restrict__ x, const float* __restrict__ w,
                        const float* __restrict__ b, int n) {
    int t = blockIdx.x * blockDim.x + threadIdx.x;
    if (t >= n * DH) return;
    int i = t / DH, j = t % DH;
    float x0 = x[i * 3 + 0], x1 = x[i * 3 + 1], x2 = x[i * 3 + 2];
    g_h[t] = x0 * w[0 * DH + j] + x1 * w[1 * DH + j] + x2 * w[2 * DH + j] + b[j];
}

// =====================================================================
// Zero the aggregation buffer
// =====================================================================
__global__ void k_zero_agg() {
    int t = blockIdx.x * blockDim.x + threadIdx.x;
    if (t < NN * DH) g_agg[t] = 0.f;
}

// =====================================================================
// P = h @ W1[:64], Q = h @ W1[64:]   (dual GEMM, no bias)
// 256 threads, tile 128 rows x 64 cols, 8x4 micro-tile
// smem: As[128*64] + Ws[64*64] = 48KB
// =====================================================================
__global__ void k_pq(const float* __restrict__ w1, int n) {
    extern __shared__ float sm[];
    float* As = sm;             // [128][64]
    float* Ws = sm + 128 * DH;  // [64][64]
    int t = threadIdx.x;
    int base = blockIdx.x * 128;

    // stage A (h tile), coalesced float4
    #pragma unroll
    for (int it = 0; it < 8; it++) {
        int q = it * 256 + t;
        int i = q >> 4, j4 = (q & 15) * 4;
        float4 v = make_float4(0.f, 0.f, 0.f, 0.f);
        if (base + i < n) v = *(const float4*)&g_h[(base + i) * DH + j4];
        *(float4*)&As[i * DH + j4] = v;
    }

    int tx = t & 15, ty = t >> 4;
    int j0 = tx * 4, i0 = ty * 8;

    for (int pass = 0; pass < 2; pass++) {
        __syncthreads();
        const float* wsrc = w1 + pass * 64 * DH;
        #pragma unroll
        for (int it = 0; it < 4; it++) {
            int q = it * 256 + t;
            int k = q >> 4, j4 = (q & 15) * 4;
            *(float4*)&Ws[k * DH + j4] = *(const float4*)&wsrc[k * DH + j4];
        }
        __syncthreads();

        float acc[8][4];
        #pragma unroll
        for (int r = 0; r < 8; r++)
            #pragma unroll
            for (int c = 0; c < 4; c++) acc[r][c] = 0.f;

        #pragma unroll 4
        for (int k = 0; k < 64; k++) {
            float4 w = *(const float4*)&Ws[k * DH + j0];
            #pragma unroll
            for (int r = 0; r < 8; r++) {
                float a = As[(i0 + r) * DH + k];
                acc[r][0] += a * w.x; acc[r][1] += a * w.y;
                acc[r][2] += a * w.z; acc[r][3] += a * w.w;
            }
        }

        float* dst = (pass == 0) ? g_P : g_Q;
        #pragma unroll
        for (int r = 0; r < 8; r++) {
            int i = base + i0 + r;
            if (i < n)
                *(float4*)&dst[i * DH + j0] =
                    make_float4(acc[r][0], acc[r][1], acc[r][2], acc[r][3]);
        }
    }
}

// =====================================================================
// Edge kernel (dominant): hid = relu(P[row] + Q[col] + b1);
//                         m = hid @ W2 + b2; atomicAdd into agg[col]
// 256 threads, 128 edges/block. smem ~50KB (needs attribute)
// =====================================================================
__global__ void k_edge(const int* __restrict__ row, const int* __restrict__ col,
                       const float* __restrict__ b1, const float* __restrict__ w2,
                       const float* __restrict__ b2, int e_total) {
    extern __shared__ float sm[];
    float* hid = sm;                 // [128][64]
    float* Ws  = sm + 128 * DH;      // [64][64]
    float* b2s = Ws + 64 * DH;       // [64]
    float* b1s = b2s + 64;           // [64]
    int*   cls = (int*)(b1s + 64);   // [128]
    int t = threadIdx.x;
    int base = blockIdx.x * 128;

    if (t < 64) { b2s[t] = b2[t]; b1s[t] = b1[t]; }
    if (t < 128) cls[t] = (base + t < e_total) ? col[base + t] : 0;

    // load W2
    #pragma unroll
    for (int it = 0; it < 4; it++) {
        int q = it * 256 + t;
        int k = q >> 4, j4 = (q & 15) * 4;
        *(float4*)&Ws[k * DH + j4] = *(const float4*)&w2[k * DH + j4];
    }
    __syncthreads();

    // stage 1: gather + add + bias + relu -> hid
    #pragma unroll
    for (int it = 0; it < 8; it++) {
        int q = it * 256 + t;
        int e = q >> 4, j4 = (q & 15) * 4;
        int ge = base + e;
        float4 hv = make_float4(0.f, 0.f, 0.f, 0.f);
        if (ge < e_total) {
            int rr = row[ge], cc = col[ge];
            float4 p  = *(const float4*)&g_P[rr * DH + j4];
            float4 qv = *(const float4*)&g_Q[cc * DH + j4];
            hv.x = fmaxf(p.x + qv.x + b1s[j4 + 0], 0.f);
            hv.y = fmaxf(p.y + qv.y + b1s[j4 + 1], 0.f);
            hv.z = fmaxf(p.z + qv.z + b1s[j4 + 2], 0.f);
            hv.w = fmaxf(p.w + qv.w + b1s[j4 + 3], 0.f);
        }
        *(float4*)&hid[e * DH + j4] = hv;
    }
    __syncthreads();

    int tx = t & 15, ty = t >> 4;
    int j0 = tx * 4, e0 = ty * 8;
    float acc[8][4];
    #pragma unroll
    for (int r = 0; r < 8; r++) {
        acc[r][0] = b2s[j0 + 0]; acc[r][1] = b2s[j0 + 1];
        acc[r][2] = b2s[j0 + 2]; acc[r][3] = b2s[j0 + 3];
    }

    #pragma unroll 4
    for (int k = 0; k < 64; k++) {
        float4 w = *(const float4*)&Ws[k * DH + j0];
        #pragma unroll
        for (int r = 0; r < 8; r++) {
            float a = hid[(e0 + r) * DH + k];
            acc[r][0] += a * w.x; acc[r][1] += a * w.y;
            acc[r][2] += a * w.z; acc[r][3] += a * w.w;
        }
    }

    // scatter-add
    #pragma unroll
    for (int r = 0; r < 8; r++) {
        int ge = base + e0 + r;
        if (ge < e_total) {
            float* dst = &g_agg[cls[e0 + r] * DH + j0];
            atomicAdd(dst + 0, acc[r][0]);
            atomicAdd(dst + 1, acc[r][1]);
            atomicAdd(dst + 2, acc[r][2]);
            atomicAdd(dst + 3, acc[r][3]);
        }
    }
}

// =====================================================================
// Node update: h = relu( relu(h@U1a + agg@U1b + b1) @ U2 + b2 )   (in place)
// =====================================================================
__global__ void k_update(const float* __restrict__ u1, const float* __restrict__ ub1,
                         const float* __restrict__ u2, const float* __restrict__ ub2,
                         int n) {
    extern __shared__ float sm[];
    float* As  = sm;             // [128][64]
    float* Ws  = sm + 128 * DH;  // [64][64]
    float* b1s = Ws + 64 * DH;
    float* b2s = b1s + 64;
    int t = threadIdx.x;
    int base = blockIdx.x * 128;
    if (t < 64) { b1s[t] = ub1[t]; b2s[t] = ub2[t]; }

    int tx = t & 15, ty = t >> 4;
    int j0 = tx * 4, i0 = ty * 8;

    float acc[8][4];
    #pragma unroll
    for (int r = 0; r < 8; r++)
        #pragma unroll
        for (int c = 0; c < 4; c++) acc[r][c] = 0.f;

    for (int pass = 0; pass < 2; pass++) {
        __syncthreads();
        const float* a_src = (pass == 0) ? g_h : g_agg;
        #pragma unroll
        for (int it = 0; it < 8; it++) {
            int q = it * 256 + t;
            int i = q >> 4, j4 = (q & 15) * 4;
            float4 v = make_float4(0.f, 0.f, 0.f, 0.f);
            if (base + i < n) v = *(const float4*)&a_src[(base + i) * DH + j4];
            *(float4*)&As[i * DH + j4] = v;
        }
        const float* wsrc = u1 + pass * 64 * DH;
        #pragma unroll
        for (int it = 0; it < 4; it++) {
            int q = it * 256 + t;
            int k = q >> 4, j4 = (q & 15) * 4;
            *(float4*)&Ws[k * DH + j4] = *(const float4*)&wsrc[k * DH + j4];
        }
        __syncthreads();
        #pragma unroll 4
        for (int k = 0; k < 64; k++) {
            float4 w = *(const float4*)&Ws[k * DH + j0];
            #pragma unroll
            for (int r = 0; r < 8; r++) {
                float a = As[(i0 + r) * DH + k];
                acc[r][0] += a * w.x; acc[r][1] += a * w.y;
                acc[r][2] += a * w.z; acc[r][3] += a * w.w;
            }
        }
    }
    __syncthreads();

    // hid = relu(acc + b1) -> As
    #pragma unroll
    for (int r = 0; r < 8; r++) {
        float4 hv;
        hv.x = fmaxf(acc[r][0] + b1s[j0 + 0], 0.f);
        hv.y = fmaxf(acc[r][1] + b1s[j0 + 1], 0.f);
        hv.z = fmaxf(acc[r][2] + b1s[j0 + 2], 0.f);
        hv.w = fmaxf(acc[r][3] + b1s[j0 + 3], 0.f);
        *(float4*)&As[(i0 + r) * DH + j0] = hv;
    }
    // load U2 into Ws
    #pragma unroll
    for (int it = 0; it < 4; it++) {
        int q = it * 256 + t;
        int k = q >> 4, j4 = (q & 15) * 4;
        *(float4*)&Ws[k * DH + j4] = *(const float4*)&u2[k * DH + j4];
    }
    __syncthreads();

    float acc2[8][4];
    #pragma unroll
    for (int r = 0; r < 8; r++) {
        acc2[r][0] = b2s[j0 + 0]; acc2[r][1] = b2s[j0 + 1];
        acc2[r][2] = b2s[j0 + 2]; acc2[r][3] = b2s[j0 + 3];
    }
    #pragma unroll 4
    for (int k = 0; k < 64; k++) {
        float4 w = *(const float4*)&Ws[k * DH + j0];
        #pragma unroll
        for (int r = 0; r < 8; r++) {
            float a = As[(i0 + r) * DH + k];
            acc2[r][0] += a * w.x; acc2[r][1] += a * w.y;
            acc2[r][2] += a * w.z; acc2[r][3] += a * w.w;
        }
    }
    #pragma unroll
    for (int r = 0; r < 8; r++) {
        int i = base + i0 + r;
        if (i < n) {
            float4 hv;
            hv.x = fmaxf(acc2[r][0], 0.f); hv.y = fmaxf(acc2[r][1], 0.f);
            hv.z = fmaxf(acc2[r][2], 0.f); hv.w = fmaxf(acc2[r][3], 0.f);
            *(float4*)&g_h[i * DH + j0] = hv;
        }
    }
}

// =====================================================================
// Output: out = h @ out_w + out_b   ([N,64] @ [64,128])
// 256 threads, tile 64 rows x 128 cols
// =====================================================================
__global__ void k_out(const float* __restrict__ ow, const float* __restrict__ ob,
                      float* __restrict__ out, int n) {
    extern __shared__ float sm[];
    float* As = sm;            // [64][64]
    float* Ws = sm + 64 * DH;  // [64][128]
    int t = threadIdx.x;
    int base = blockIdx.x * 64;

    #pragma unroll
    for (int it = 0; it < 4; it++) {
        int q = it * 256 + t;
        int i = q >> 4, j4 = (q & 15) * 4;
        float4 v = make_float4(0.f, 0.f, 0.f, 0.f);
        if (base + i < n) v = *(const float4*)&g_h[(base + i) * DH + j4];
        *(float4*)&As[i * DH + j4] = v;
    }
    #pragma unroll
    for (int it = 0; it < 8; it++) {
        int q = it * 256 + t;
        int k = q >> 5, j4 = (q & 31) * 4;
        *(float4*)&Ws[k * 128 + j4] = *(const float4*)&ow[k * 128 + j4];
    }
    __syncthreads();

    int tx = t & 31, ty = t >> 5;
    int j0 = tx * 4, i0 = ty * 8;
    float acc[8][4];
    #pragma unroll
    for (int r = 0; r < 8; r++) {
        acc[r][0] = ob[j0 + 0]; acc[r][1] = ob[j0 + 1];
        acc[r][2] = ob[j0 + 2]; acc[r][3] = ob[j0 + 3];
    }
    #pragma unroll 4
    for (int k = 0; k < 64; k++) {
        float4 w = *(const float4*)&Ws[k * 128 + j0];
        #pragma unroll
        for (int r = 0; r < 8; r++) {
            float a = As[(i0 + r) * DH + k];
            acc[r][0] += a * w.x; acc[r][1] += a * w.y;
            acc[r][2] += a * w.z; acc[r][3] += a * w.w;
        }
    }
    #pragma unroll
    for (int r = 0; r < 8; r++) {
        int i = base + i0 + r;
        if (i < n)
            *(float4*)&out[i * 128 + j0] =
                make_float4(acc[r][0], acc[r][1], acc[r][2], acc[r][3]);
    }
}

// =====================================================================
// Launcher
// =====================================================================
extern "C" void kernel_launch(void* const* d_in, const int* in_sizes, int n_in,
                              void* d_out, int out_size) {
    const float* x      = (const float*)d_in[0];
    const int*   ei     = (const int*)  d_in[1];
    const float* in_w   = (const float*)d_in[2];
    const float* in_b   = (const float*)d_in[3];
    const float* msg_w1 = (const float*)d_in[4];
    const float* msg_b1 = (const float*)d_in[5];
    const float* msg_w2 = (const float*)d_in[6];
    const float* msg_b2 = (const float*)d_in[7];
    const float* upd_w1 = (const float*)d_in[8];
    const float* upd_b1 = (const float*)d_in[9];
    const float* upd_w2 = (const float*)d_in[10];
    const float* upd_b2 = (const float*)d_in[11];
    const float* out_w  = (const float*)d_in[12];
    const float* out_b  = (const float*)d_in[13];

    int n = in_sizes[0] / 3;
    int e = in_sizes[1] / 2;
    const int* row = ei;
    const int* col = ei + e;

    const int SMEM_PQ   = (128 * DH + 64 * DH) * 4;            // 49152
    const int SMEM_EDGE = (128 * DH + 64 * DH + 128) * 4 + 512; // 50176
    const int SMEM_UPD  = (128 * DH + 64 * DH + 128) * 4;       // 49664
    const int SMEM_OUT  = (64 * DH + 64 * 128) * 4;             // 49152

    cudaFuncSetAttribute(k_pq,     cudaFuncAttributeMaxDynamicSharedMemorySize, SMEM_PQ);
    cudaFuncSetAttribute(k_edge,   cudaFuncAttributeMaxDynamicSharedMemorySize, SMEM_EDGE);
    cudaFuncSetAttribute(k_update, cudaFuncAttributeMaxDynamicSharedMemorySize, SMEM_UPD);
    cudaFuncSetAttribute(k_out,    cudaFuncAttributeMaxDynamicSharedMemorySize, SMEM_OUT);

    k_input<<<(n * DH + 255) / 256, 256>>>(x, in_w, in_b, n);

    int nb = (n + 127) / 128;
    int eb = (e + 127) / 128;
    for (int l = 0; l < 3; l++) {
        k_pq<<<nb, 256, SMEM_PQ>>>(msg_w1 + l * 2 * DH * DH, n);
        k_zero_agg<<<(NN * DH + 255) / 256, 256>>>();
        k_edge<<<eb, 256, SMEM_EDGE>>>(row, col, msg_b1 + l * DH,
                                       msg_w2 + l * DH * DH, msg_b2 + l * DH, e);
        k_update<<<nb, 256, SMEM_UPD>>>(upd_w1 + l * 2 * DH * DH, upd_b1 + l * DH,
                                        upd_w2 + l * DH * DH, upd_b2 + l * DH, n);
    }
    k_out<<<(n + 63) / 64, 256, SMEM_OUT>>>(out_w, out_b, (float*)d_out, n);
}